// round 16
// baseline (speedup 1.0000x reference)
#include <cuda_runtime.h>

// FoldNd (col2im): B=16, C=64, K=3, H=W=128, PAD=1, STR=1, DIL=1
// R16: same mechanism as R15 (pin the 67MB output in the ~126MB L2 across
// graph replays so DRAM never sees the write traffic), using the legal
// encoding: createpolicy.fractional.L2::evict_last + st.global.L2::cache_hint.
// Reads stay __ldcs (evict-first) so the 604MB read stream evicts itself,
// not the pinned output lines.
//
// Body is the converged-best structure: gather form, one float4 per thread,
// warp = one 128-wide output row, halo via warp shuffle (9 aligned LDG.128
// + 1 STG.128, zero scalar loads), plain grid 8192 x 512.

namespace {
constexpr int H = 128;
constexpr int W = 128;
constexpr int PLANE = H * W;            // 16384
constexpr int NOUT = 16 * 64 * H * W;   // 16,777,216
constexpr int NVEC = NOUT / 4;          // 4,194,304
}

__global__ void __launch_bounds__(512) fold_vec4_pinout_kernel(
    const float* __restrict__ in, float* __restrict__ out)
{
    int v = blockIdx.x * blockDim.x + threadIdx.x;   // grid covers NVEC exactly

    int lane = v & 31;
    int w0 = lane << 2;              // 0,4,...,124 (warp spans one row)
    int h  = (v >> 5) & (H - 1);
    int bc = v >> 12;                // b*64 + c

    const float* base = in + (long long)bc * 9 * PLANE;

    float4 acc = make_float4(0.f, 0.f, 0.f, 0.f);

    #pragma unroll
    for (int kh = 0; kh < 3; ++kh) {
        int lh = h + 1 - kh;         // warp-uniform predicate
        if ((unsigned)lh < (unsigned)H) {
            const float* r0 = base + (kh * 3 + 0) * PLANE + lh * W; // kw=0
            const float* r1 = r0 + PLANE;                            // kw=1
            const float* r2 = r1 + PLANE;                            // kw=2

            float4 A  = __ldcs(reinterpret_cast<const float4*>(r0 + w0));
            float4 Bv = __ldcs(reinterpret_cast<const float4*>(r1 + w0));
            float4 Cv = __ldcs(reinterpret_cast<const float4*>(r2 + w0));

            // a4  = r0[w0+4] = next lane's A.x   (lane 31: lw=128 -> 0)
            // cm1 = r2[w0-1] = prev lane's Cv.w  (lane 0:  lw=-1  -> 0)
            float a4  = __shfl_down_sync(0xFFFFFFFFu, A.x, 1);
            float cm1 = __shfl_up_sync(0xFFFFFFFFu, Cv.w, 1);
            if (lane == 31) a4  = 0.f;
            if (lane == 0)  cm1 = 0.f;

            // output w0+j: kw0 -> elem(w0+j+1), kw1 -> elem(w0+j), kw2 -> elem(w0+j-1)
            acc.x += A.y + Bv.x + cm1;
            acc.y += A.z + Bv.y + Cv.x;
            acc.z += A.w + Bv.z + Cv.y;
            acc.w += a4  + Bv.w + Cv.z;
        }
    }

    // evict_last policy store: keep output lines L2-resident across replays
    unsigned long long policy;
    asm("createpolicy.fractional.L2::evict_last.b64 %0, 1.0;" : "=l"(policy));
    float4* p = reinterpret_cast<float4*>(out) + v;
    asm volatile("st.global.L2::cache_hint.v4.f32 [%0], {%1,%2,%3,%4}, %5;"
                 :: "l"(p), "f"(acc.x), "f"(acc.y), "f"(acc.z), "f"(acc.w),
                    "l"(policy)
                 : "memory");
}

extern "C" void kernel_launch(void* const* d_in, const int* in_sizes, int n_in,
                              void* d_out, int out_size)
{
    const float* in = (const float*)d_in[0];
    float* out = (float*)d_out;
    const int threads = 512;
    const int blocks = NVEC / threads;   // exact: 8192 blocks
    fold_vec4_pinout_kernel<<<blocks, threads>>>(in, out);
}

// round 17
// speedup vs baseline: 1.0140x; 1.0140x over previous
#include <cuda_runtime.h>

// FoldNd (col2im): B=16, C=64, K=3, H=W=128, PAD=1, STR=1, DIL=1
// FINAL — converged at the LTS (L2-fabric) throughput ceiling.
//   traffic floor: 604 MB read (once) + 67 MB write (once) = 671 MB, all of
//     which must traverse L2 (no bypass path). Proven minimal: adjacent
//     output rows touch disjoint input addresses -> zero reuse exists.
//   LTS cap: ~6300 B/cyc ≈ 6.95 TB/s (path-independent) => 96.5 us floor.
//   Measured band: 96.0-97.0 us across 9 runs. R16 proved DRAM-writeback
//   elimination (evict_last pinning) cannot help: DRAM% fell, L2% rose,
//   wall time did not improve — LTS is the wall.
//
// Structure (each element A/B-measured):
//  - gather form, no atomics; one float4 of output per thread
//  - warp = one 128-wide output row: +/-1 halo elements from neighbor lanes
//    via warp shuffle -> exactly 9 aligned LDG.128 + 1 STG.128 per thread
//    (vec8 regressed via occupancy; load front-batching neutral)
//  - __ldcs evict-first reads, __stcs stores (__stwt and evict_last both
//    regressed in steady-state graph replay)
//  - plain grid 8192 x 512 (persistent grid-stride regressed twice)

namespace {
constexpr int H = 128;
constexpr int W = 128;
constexpr int PLANE = H * W;            // 16384
constexpr int NOUT = 16 * 64 * H * W;   // 16,777,216
constexpr int NVEC = NOUT / 4;          // 4,194,304
}

__global__ void __launch_bounds__(512) fold_vec4_stream_kernel(
    const float* __restrict__ in, float* __restrict__ out)
{
    int v = blockIdx.x * blockDim.x + threadIdx.x;   // grid covers NVEC exactly

    int lane = v & 31;
    int w0 = lane << 2;              // 0,4,...,124 (warp spans one row)
    int h  = (v >> 5) & (H - 1);
    int bc = v >> 12;                // b*64 + c

    const float* base = in + (long long)bc * 9 * PLANE;

    float4 acc = make_float4(0.f, 0.f, 0.f, 0.f);

    #pragma unroll
    for (int kh = 0; kh < 3; ++kh) {
        int lh = h + 1 - kh;         // warp-uniform predicate
        if ((unsigned)lh < (unsigned)H) {
            const float* r0 = base + (kh * 3 + 0) * PLANE + lh * W; // kw=0
            const float* r1 = r0 + PLANE;                            // kw=1
            const float* r2 = r1 + PLANE;                            // kw=2

            float4 A  = __ldcs(reinterpret_cast<const float4*>(r0 + w0));
            float4 Bv = __ldcs(reinterpret_cast<const float4*>(r1 + w0));
            float4 Cv = __ldcs(reinterpret_cast<const float4*>(r2 + w0));

            // a4  = r0[w0+4] = next lane's A.x   (lane 31: lw=128 -> 0)
            // cm1 = r2[w0-1] = prev lane's Cv.w  (lane 0:  lw=-1  -> 0)
            float a4  = __shfl_down_sync(0xFFFFFFFFu, A.x, 1);
            float cm1 = __shfl_up_sync(0xFFFFFFFFu, Cv.w, 1);
            if (lane == 31) a4  = 0.f;
            if (lane == 0)  cm1 = 0.f;

            // output w0+j: kw0 -> elem(w0+j+1), kw1 -> elem(w0+j), kw2 -> elem(w0+j-1)
            acc.x += A.y + Bv.x + cm1;
            acc.y += A.z + Bv.y + Cv.x;
            acc.z += A.w + Bv.z + Cv.y;
            acc.w += a4  + Bv.w + Cv.z;
        }
    }

    __stcs(reinterpret_cast<float4*>(out) + v, acc);
}

extern "C" void kernel_launch(void* const* d_in, const int* in_sizes, int n_in,
                              void* d_out, int out_size)
{
    const float* in = (const float*)d_in[0];
    float* out = (float*)d_out;
    const int threads = 512;
    const int blocks = NVEC / threads;   // exact: 8192 blocks
    fold_vec4_stream_kernel<<<blocks, threads>>>(in, out);
}